// round 3
// baseline (speedup 1.0000x reference)
#include <cuda_runtime.h>
#include <cstdint>

// Problem constants
#define BATCH   32768
#define DIMS    64          // D
#define HID     64          // H
#define NMLP    63          // D-1 stacked MLPs
#define TILE_B  128         // batch rows per CTA
#define NTILES  (BATCH / TILE_B)   // 256
#define THREADS 256

// smem layout (float offsets). Strides padded to 72 floats: B-fragment LDS
// conflict-free (bank = 8*row+col), A-fragment 2-way (known, revisit w/ ncu).
#define OFF_XS   0            // [128][72] X tile (tf32)
#define OFF_HS   9216         // [128][72] h1 tile (tf32)
#define OFF_WA   18432        // [64][72]  W1 buffer
#define OFF_WB   23040        // [64][72]  W2 buffer
#define OFF_B1   27648        // [64]
#define OFF_B2   27712        // [64]
#define OFF_W3   27776        // [64]
#define OFF_PART 27840        // [128] cross-warp dot partials
#define OFF_S0   27968        // [64] dim0 scratch
#define OFF_S1   28032        // [64]
#define OFF_O0   28096        // [1]
#define SMEM_FLOATS 28100
#define SMEM_BYTES  (SMEM_FLOATS * 4)

__device__ __forceinline__ float to_tf32(float x) {
    uint32_t u;
    asm("cvt.rna.tf32.f32 %0, %1;" : "=r"(u) : "f"(x));
    return __uint_as_float(u);
}

__global__ __launch_bounds__(THREADS, 2)
void mlplist_kernel(const float* __restrict__ inputs,
                    const float* __restrict__ W1, const float* __restrict__ b1,
                    const float* __restrict__ W2, const float* __restrict__ b2,
                    const float* __restrict__ W3, const float* __restrict__ b3,
                    const float* __restrict__ w01, const float* __restrict__ b01,
                    const float* __restrict__ w02, const float* __restrict__ b02,
                    const float* __restrict__ w03, const float* __restrict__ b03,
                    float* __restrict__ out) {
    extern __shared__ float sm[];
    float* XS = sm + OFF_XS;
    float* HS = sm + OFF_HS;
    float* WA = sm + OFF_WA;
    float* WB = sm + OFF_WB;
    float* B1S = sm + OFF_B1;
    float* B2S = sm + OFF_B2;
    float* W3S = sm + OFF_W3;
    float* PART = sm + OFF_PART;
    float* S0 = sm + OFF_S0;
    float* S1 = sm + OFF_S1;
    float* O0 = sm + OFF_O0;

    const int tid  = threadIdx.x;
    const int bx   = blockIdx.x;
    const int warp = tid >> 5, lane = tid & 31;
    const int wM = warp >> 1;       // 0..3 : rows [wM*32, wM*32+32)
    const int wN = warp & 1;        // 0..1 : cols [wN*32, wN*32+32)
    const int qr = lane >> 2;       // 0..7
    const int qc = lane & 3;        // 0..3

    // cp.async one 64x64 fp32 weight matrix into a [64][72] smem buffer
    auto issue_w = [&](const float* g, float* s) {
        #pragma unroll
        for (int it = 0; it < 4; it++) {
            int e = tid + it * 256;            // 1024 chunks of 16B
            int row = e >> 4, cv = e & 15;
            uint32_t da = (uint32_t)__cvta_generic_to_shared(s + row * 72 + cv * 4);
            asm volatile("cp.async.cg.shared.global [%0], [%1], 16;"
                         :: "r"(da), "l"(g + row * 64 + cv * 4));
        }
        asm volatile("cp.async.commit_group;" ::: "memory");
    };

    // 128x64 = A[128xK] * B[Kx64] via m16n8k8 tf32 mma, K = kblocks*8
    auto gemm = [&](const float* As, const float* Bs, int kblocks, float (&c)[2][4][4]) {
        for (int kb = 0; kb < kblocks; kb++) {
            uint32_t a[2][4];
            const float* ab = As + (wM * 32 + qr) * 72 + kb * 8 + qc;
            #pragma unroll
            for (int mt = 0; mt < 2; mt++) {
                const float* ap = ab + mt * 16 * 72;
                a[mt][0] = __float_as_uint(ap[0]);
                a[mt][1] = __float_as_uint(ap[8 * 72]);
                a[mt][2] = __float_as_uint(ap[4]);
                a[mt][3] = __float_as_uint(ap[8 * 72 + 4]);
            }
            const float* bb = Bs + (kb * 8 + qc) * 72 + wN * 32 + qr;
            #pragma unroll
            for (int nt = 0; nt < 4; nt++) {
                uint32_t bf0 = __float_as_uint(bb[nt * 8]);
                uint32_t bf1 = __float_as_uint(bb[4 * 72 + nt * 8]);
                #pragma unroll
                for (int mt = 0; mt < 2; mt++) {
                    asm volatile(
                        "mma.sync.aligned.m16n8k8.row.col.f32.tf32.tf32.f32 "
                        "{%0,%1,%2,%3},{%4,%5,%6,%7},{%8,%9},{%0,%1,%2,%3};"
                        : "+f"(c[mt][nt][0]), "+f"(c[mt][nt][1]),
                          "+f"(c[mt][nt][2]), "+f"(c[mt][nt][3])
                        : "r"(a[mt][0]), "r"(a[mt][1]), "r"(a[mt][2]), "r"(a[mt][3]),
                          "r"(bf0), "r"(bf1));
                }
            }
        }
    };

    // ---------------- Prologue ----------------
    issue_w(W1, WA);            // group: W1(0)
    issue_w(W2, WB);            // group: W2(0)

    // dim-0 MLP stage 1 (constant, redundant per CTA, tiny)
    if (tid < 64) {
        float acc = b01[tid];
        #pragma unroll
        for (int k = 0; k < 10; k++) {
            float v = (float)(0.1 * (-5.0 + 10.0 * (double)k / 9.0));
            acc += v * w01[k * 64 + tid];
        }
        S0[tid] = fmaxf(acc, 0.f);
    }

    // Load X tile (convert to tf32 once)
    {
        const float4* gx = (const float4*)(inputs + (size_t)bx * TILE_B * DIMS);
        #pragma unroll
        for (int it = 0; it < 8; it++) {
            int e = tid + it * 256;       // 2048 float4
            float4 v = gx[e];
            int idx = e * 4;
            int row = idx >> 6, col = idx & 63;
            float* d = XS + row * 72 + col;
            d[0] = to_tf32(v.x); d[1] = to_tf32(v.y);
            d[2] = to_tf32(v.z); d[3] = to_tf32(v.w);
        }
    }
    __syncthreads();

    if (tid < 64) {
        float acc = b02[tid];
        #pragma unroll 8
        for (int k = 0; k < 64; k++) acc += S0[k] * w02[k * 64 + tid];
        S1[tid] = fmaxf(acc, 0.f);
    }
    __syncthreads();
    if (tid == 0) {
        float acc = b03[0];
        #pragma unroll 8
        for (int k = 0; k < 64; k++) acc += S1[k] * w03[k];
        O0[0] = acc;
    }
    __syncthreads();
    if (tid < TILE_B) out[(size_t)(bx * TILE_B + tid) * DIMS] = O0[0];

    // ---------------- Main loop over the 63 MLPs ----------------
    for (int r = 0; r < NMLP; r++) {
        // W1(r) is the oldest pending group; allow 1 (W2(r)) to stay in flight
        asm volatile("cp.async.wait_group 1;" ::: "memory");
        __syncthreads();

        // mask: zero W1 rows j in [r+1, kblocks*8)
        const int kblocks = (r >> 3) + 1;
        {
            int zs = r + 1, ze = kblocks << 3;
            int nz = (ze - zs) * 64;
            for (int e = tid; e < nz; e += THREADS)
                WA[(zs + (e >> 6)) * 72 + (e & 63)] = 0.f;
        }
        if (tid < 64) {
            B1S[tid] = b1[r * 64 + tid];
            B2S[tid] = b2[r * 64 + tid];
            W3S[tid] = W3[r * 64 + tid];
        }
        const float b3v = b3[r];
        __syncthreads();

        // GEMM1: h1 = relu(X * W1m + b1)
        float c[2][4][4];
        #pragma unroll
        for (int mt = 0; mt < 2; mt++)
            #pragma unroll
            for (int nt = 0; nt < 4; nt++)
                #pragma unroll
                for (int j = 0; j < 4; j++) c[mt][nt][j] = 0.f;
        gemm(XS, WA, kblocks, c);

        #pragma unroll
        for (int mt = 0; mt < 2; mt++) {
            int row0 = wM * 32 + mt * 16 + qr;
            #pragma unroll
            for (int nt = 0; nt < 4; nt++) {
                int col0 = wN * 32 + nt * 8 + qc * 2;
                float2 lo, hi;
                lo.x = to_tf32(fmaxf(c[mt][nt][0] + B1S[col0], 0.f));
                lo.y = to_tf32(fmaxf(c[mt][nt][1] + B1S[col0 + 1], 0.f));
                hi.x = to_tf32(fmaxf(c[mt][nt][2] + B1S[col0], 0.f));
                hi.y = to_tf32(fmaxf(c[mt][nt][3] + B1S[col0 + 1], 0.f));
                *(float2*)&HS[row0 * 72 + col0] = lo;
                *(float2*)&HS[(row0 + 8) * 72 + col0] = hi;
            }
        }
        __syncthreads();   // HS ready; WA free

        // prefetch W1(r+1) into WA, then make sure W2(r) has landed
        if (r + 1 < NMLP) {
            issue_w(W1 + (size_t)(r + 1) * 4096, WA);
            asm volatile("cp.async.wait_group 1;" ::: "memory");
        } else {
            asm volatile("cp.async.wait_group 0;" ::: "memory");
        }
        __syncthreads();

        // GEMM2 + fused GEMM3: o = relu(h1*W2 + b2) . w3 + b3
        #pragma unroll
        for (int mt = 0; mt < 2; mt++)
            #pragma unroll
            for (int nt = 0; nt < 4; nt++)
                #pragma unroll
                for (int j = 0; j < 4; j++) c[mt][nt][j] = 0.f;
        gemm(HS, WB, 8, c);

        float p[2][2] = {{0.f, 0.f}, {0.f, 0.f}};
        #pragma unroll
        for (int mt = 0; mt < 2; mt++) {
            #pragma unroll
            for (int nt = 0; nt < 4; nt++) {
                int col0 = wN * 32 + nt * 8 + qc * 2;
                float w3a = W3S[col0], w3b = W3S[col0 + 1];
                float ba = B2S[col0], bb2 = B2S[col0 + 1];
                p[mt][0] += fmaxf(c[mt][nt][0] + ba, 0.f) * w3a
                          + fmaxf(c[mt][nt][1] + bb2, 0.f) * w3b;
                p[mt][1] += fmaxf(c[mt][nt][2] + ba, 0.f) * w3a
                          + fmaxf(c[mt][nt][3] + bb2, 0.f) * w3b;
            }
        }
        // reduce over the 4 lanes of each quad (same row, different cols)
        #pragma unroll
        for (int mt = 0; mt < 2; mt++)
            #pragma unroll
            for (int h = 0; h < 2; h++) {
                p[mt][h] += __shfl_xor_sync(0xffffffffu, p[mt][h], 1);
                p[mt][h] += __shfl_xor_sync(0xffffffffu, p[mt][h], 2);
            }
        if (wN == 0 && qc == 0) {
            #pragma unroll
            for (int mt = 0; mt < 2; mt++) {
                PART[wM * 32 + mt * 16 + qr]     = p[mt][0];
                PART[wM * 32 + mt * 16 + qr + 8] = p[mt][1];
            }
        }
        __syncthreads();
        if (wN == 1 && qc == 0) {
            #pragma unroll
            for (int mt = 0; mt < 2; mt++) {
                int row0 = wM * 32 + mt * 16 + qr;
                float o0v = PART[row0] + p[mt][0] + b3v;
                float o1v = PART[row0 + 8] + p[mt][1] + b3v;
                out[(size_t)(bx * TILE_B + row0) * DIMS + (r + 1)] = o0v;
                out[(size_t)(bx * TILE_B + row0 + 8) * DIMS + (r + 1)] = o1v;
            }
        }
        // prefetch W2(r+1) (WB reads finished before the sync above)
        if (r + 1 < NMLP) issue_w(W2 + (size_t)(r + 1) * 4096, WB);
    }
}

extern "C" void kernel_launch(void* const* d_in, const int* in_sizes, int n_in,
                              void* d_out, int out_size) {
    const float* inputs = (const float*)d_in[0];
    const float* W1  = (const float*)d_in[1];
    const float* b1  = (const float*)d_in[2];
    const float* W2  = (const float*)d_in[3];
    const float* b2  = (const float*)d_in[4];
    const float* W3  = (const float*)d_in[5];
    const float* b3  = (const float*)d_in[6];
    const float* w01 = (const float*)d_in[7];
    const float* b01 = (const float*)d_in[8];
    const float* w02 = (const float*)d_in[9];
    const float* b02 = (const float*)d_in[10];
    const float* w03 = (const float*)d_in[11];
    const float* b03 = (const float*)d_in[12];
    float* out = (float*)d_out;

    cudaFuncSetAttribute(mlplist_kernel,
                         cudaFuncAttributeMaxDynamicSharedMemorySize, SMEM_BYTES);
    mlplist_kernel<<<NTILES, THREADS, SMEM_BYTES>>>(
        inputs, W1, b1, W2, b2, W3, b3,
        w01, b01, w02, b02, w03, b03, out);
}

// round 5
// speedup vs baseline: 1.3027x; 1.3027x over previous
#include <cuda_runtime.h>
#include <cstdint>

#define DIMS    64
#define HID     64
#define NMLP    63
#define TILE_B  128
#define NTILES  256
#define THREADS 256

// Scratch: fragment-major, tf32-rounded, mask-baked weights.
// Layout per r: [kb][nt][lane] float2 = (W[kb*8+qc][nt*8+qr], W[kb*8+qc+4][nt*8+qr])
__device__ float g_w1f[NMLP][4096];
__device__ float g_w2f[NMLP][4096];
__device__ float g_o0d;

__device__ __forceinline__ float to_tf32(float x) {
    uint32_t u;
    asm("cvt.rna.tf32.f32 %0, %1;" : "=r"(u) : "f"(x));
    return __uint_as_float(u);
}

// ---------------- Preprocess: mask + tf32 + fragment-major relayout ----------------
__global__ void prep_kernel(const float* __restrict__ W1, const float* __restrict__ W2,
                            const float* __restrict__ w01, const float* __restrict__ b01,
                            const float* __restrict__ w02, const float* __restrict__ b02,
                            const float* __restrict__ w03, const float* __restrict__ b03) {
    __shared__ float sw[4096];
    const int r = blockIdx.x, tid = threadIdx.x;

    for (int i = tid; i < 4096; i += THREADS) sw[i] = W1[r * 4096 + i];
    __syncthreads();
    for (int e = tid; e < 2048; e += THREADS) {
        int lane = e & 31, nt = (e >> 5) & 7, kb = e >> 8;
        int qr = lane >> 2, qc = lane & 3;
        int k0 = kb * 8 + qc, n = nt * 8 + qr;
        g_w1f[r][2 * e]     = (k0     <= r) ? to_tf32(sw[k0 * 64 + n])       : 0.f;
        g_w1f[r][2 * e + 1] = (k0 + 4 <= r) ? to_tf32(sw[(k0 + 4) * 64 + n]) : 0.f;
    }
    __syncthreads();
    for (int i = tid; i < 4096; i += THREADS) sw[i] = W2[r * 4096 + i];
    __syncthreads();
    for (int e = tid; e < 2048; e += THREADS) {
        int lane = e & 31, nt = (e >> 5) & 7, kb = e >> 8;
        int qr = lane >> 2, qc = lane & 3;
        int k0 = kb * 8 + qc, n = nt * 8 + qr;
        g_w2f[r][2 * e]     = to_tf32(sw[k0 * 64 + n]);
        g_w2f[r][2 * e + 1] = to_tf32(sw[(k0 + 4) * 64 + n]);
    }
    if (r == 0) {   // dim-0 constant MLP, once for the whole grid
        __syncthreads();
        if (tid < 64) {
            float acc = b01[tid];
            #pragma unroll
            for (int k = 0; k < 10; k++) {
                float v = (float)(0.1 * (-5.0 + 10.0 * (double)k / 9.0));
                acc += v * w01[k * 64 + tid];
            }
            sw[tid] = fmaxf(acc, 0.f);
        }
        __syncthreads();
        if (tid < 64) {
            float acc = b02[tid];
            #pragma unroll 8
            for (int k = 0; k < 64; k++) acc += sw[k] * w02[k * 64 + tid];
            sw[64 + tid] = fmaxf(acc, 0.f);
        }
        __syncthreads();
        if (tid == 0) {
            float acc = b03[0];
            #pragma unroll 8
            for (int k = 0; k < 64; k++) acc += sw[64 + k] * w03[k];
            g_o0d = acc;
        }
    }
}

// ---------------- Main kernel ----------------
// smem: w1buf[2][4096] | w2buf[2][4096] | biasbuf[2][192] (b1|b2|w3)
#define SM_W1   0
#define SM_W2   8192
#define SM_BS   16384
#define SMEM_FLOATS (16384 + 384)
#define SMEM_BYTES  (SMEM_FLOATS * 4)

__device__ __forceinline__ void mma8(float* c, const uint32_t* a, uint32_t b0, uint32_t b1) {
    asm volatile(
        "mma.sync.aligned.m16n8k8.row.col.f32.tf32.tf32.f32 "
        "{%0,%1,%2,%3},{%4,%5,%6,%7},{%8,%9},{%0,%1,%2,%3};"
        : "+f"(c[0]), "+f"(c[1]), "+f"(c[2]), "+f"(c[3])
        : "r"(a[0]), "r"(a[1]), "r"(a[2]), "r"(a[3]), "r"(b0), "r"(b1));
}

__global__ __launch_bounds__(THREADS, 2)
void mlplist_kernel(const float* __restrict__ inputs,
                    const float* __restrict__ b1g, const float* __restrict__ b2g,
                    const float* __restrict__ W3g, const float* __restrict__ b3g,
                    float* __restrict__ out) {
    extern __shared__ float sm[];
    const int tid = threadIdx.x, bx = blockIdx.x;
    const int warp = tid >> 5, lane = tid & 31;
    const int qr = lane >> 2, qc = lane & 3;
    const int rowbase = bx * TILE_B + warp * 16;

    auto issue_r = [&](int rn, int st) {
        {   // W1 fragments: only the kblocks actually used
            int n16 = ((rn >> 3) + 1) * 128;          // 16B chunks
            float* d = sm + SM_W1 + st * 4096;
            const float* s = g_w1f[rn];
            for (int c = tid; c < n16; c += THREADS) {
                uint32_t da = (uint32_t)__cvta_generic_to_shared(d + c * 4);
                asm volatile("cp.async.cg.shared.global [%0], [%1], 16;" :: "r"(da), "l"(s + c * 4));
            }
        }
        {   // W2 fragments: full 16KB
            float* d = sm + SM_W2 + st * 4096;
            const float* s = g_w2f[rn];
            #pragma unroll
            for (int it = 0; it < 4; it++) {
                int c = tid + it * THREADS;
                uint32_t da = (uint32_t)__cvta_generic_to_shared(d + c * 4);
                asm volatile("cp.async.cg.shared.global [%0], [%1], 16;" :: "r"(da), "l"(s + c * 4));
            }
        }
        if (tid < 48) {   // b1 | b2 | w3
            const float* s = (tid < 16) ? (b1g + rn * 64 + tid * 4)
                           : (tid < 32) ? (b2g + rn * 64 + (tid - 16) * 4)
                                        : (W3g + rn * 64 + (tid - 32) * 4);
            float* d = sm + SM_BS + st * 192 + tid * 4;
            uint32_t da = (uint32_t)__cvta_generic_to_shared(d);
            asm volatile("cp.async.cg.shared.global [%0], [%1], 16;" :: "r"(da), "l"(s));
        }
        asm volatile("cp.async.commit_group;" ::: "memory");
    };

    // ---- Prologue: X fragments into registers (loaded once, reused 63x) ----
    uint32_t xa[8][4];
    {
        const float* xb = inputs + (size_t)rowbase * 64;
        #pragma unroll
        for (int kb = 0; kb < 8; kb++) {
            int c0 = kb * 8 + qc;
            xa[kb][0] = __float_as_uint(to_tf32(xb[qr * 64 + c0]));
            xa[kb][1] = __float_as_uint(to_tf32(xb[(qr + 8) * 64 + c0]));
            xa[kb][2] = __float_as_uint(to_tf32(xb[qr * 64 + c0 + 4]));
            xa[kb][3] = __float_as_uint(to_tf32(xb[(qr + 8) * 64 + c0 + 4]));
        }
    }
    issue_r(0, 0);

    // column 0 (constant dim-0 MLP output)
    {
        float o0 = g_o0d;
        if (tid < TILE_B) out[(size_t)(bx * TILE_B + tid) * 64] = o0;
    }

    const int src0 = (lane & ~3) | (qc >> 1);
    const int src1 = src0 + 2;
    const bool odd = qc & 1;

    for (int r = 0; r < NMLP; r++) {
        const int st = r & 1;
        __syncthreads();                       // all warps done with stage st^1 (iter r-1)
        if (r + 1 < NMLP) {
            issue_r(r + 1, st ^ 1);
            asm volatile("cp.async.wait_group 1;" ::: "memory");
        } else {
            asm volatile("cp.async.wait_group 0;" ::: "memory");
        }
        __syncthreads();                       // stage st visible to all warps

        const float2* w1p = (const float2*)(sm + SM_W1 + st * 4096) + lane;
        const float2* w2p = (const float2*)(sm + SM_W2 + st * 4096) + lane;
        const float* bs = sm + SM_BS + st * 192;
        const float b3v = __ldg(b3g + r);
        const int kbl = (r >> 3) + 1;

        // ---- GEMM1 (X regs * W1frag) + epilogue + shfl transpose -> a2 ----
        uint32_t a2[8][4];
        #pragma unroll
        for (int ntg = 0; ntg < 8; ntg += 4) {
            float c1[4][4];
            #pragma unroll
            for (int i = 0; i < 4; i++)
                #pragma unroll
                for (int j = 0; j < 4; j++) c1[i][j] = 0.f;
            for (int kb = 0; kb < kbl; kb++) {
                #pragma unroll
                for (int i = 0; i < 4; i++) {
                    float2 b = w1p[(kb * 8 + ntg + i) * 32];
                    mma8(c1[i], xa[kb], __float_as_uint(b.x), __float_as_uint(b.y));
                }
            }
            #pragma unroll
            for (int i = 0; i < 4; i++) {
                int nt = ntg + i;
                float2 bb = *(const float2*)(bs + nt * 8 + 2 * qc);
                float v0 = to_tf32(fmaxf(c1[i][0] + bb.x, 0.f));
                float v1 = to_tf32(fmaxf(c1[i][1] + bb.y, 0.f));
                float v2 = to_tf32(fmaxf(c1[i][2] + bb.x, 0.f));
                float v3 = to_tf32(fmaxf(c1[i][3] + bb.y, 0.f));
                // c-layout (g,2t),(g,2t+1),(g+8,2t),(g+8,2t+1) -> a-layout (g,t),(g+8,t),(g,t+4),(g+8,t+4)
                float t0 = __shfl_sync(~0u, v0, src0), t1 = __shfl_sync(~0u, v1, src0);
                float t2 = __shfl_sync(~0u, v2, src0), t3 = __shfl_sync(~0u, v3, src0);
                float u0 = __shfl_sync(~0u, v0, src1), u1 = __shfl_sync(~0u, v1, src1);
                float u2 = __shfl_sync(~0u, v2, src1), u3 = __shfl_sync(~0u, v3, src1);
                a2[nt][0] = __float_as_uint(odd ? t1 : t0);
                a2[nt][1] = __float_as_uint(odd ? t3 : t2);
                a2[nt][2] = __float_as_uint(odd ? u1 : u0);
                a2[nt][3] = __float_as_uint(odd ? u3 : u2);
            }
        }

        // ---- GEMM2 (a2 * W2frag) + fused GEMM3 dot ----
        float p0 = 0.f, p1 = 0.f;
        #pragma unroll
        for (int ntg = 0; ntg < 8; ntg += 4) {
            float c2[4][4];
            #pragma unroll
            for (int i = 0; i < 4; i++)
                #pragma unroll
                for (int j = 0; j < 4; j++) c2[i][j] = 0.f;
            #pragma unroll
            for (int kb = 0; kb < 8; kb++) {
                #pragma unroll
                for (int i = 0; i < 4; i++) {
                    float2 b = w2p[(kb * 8 + ntg + i) * 32];
                    mma8(c2[i], a2[kb], __float_as_uint(b.x), __float_as_uint(b.y));
                }
            }
            #pragma unroll
            for (int i = 0; i < 4; i++) {
                int nt = ntg + i;
                float2 bb = *(const float2*)(bs + 64 + nt * 8 + 2 * qc);
                float2 ww = *(const float2*)(bs + 128 + nt * 8 + 2 * qc);
                p0 += fmaxf(c2[i][0] + bb.x, 0.f) * ww.x + fmaxf(c2[i][1] + bb.y, 0.f) * ww.y;
                p1 += fmaxf(c2[i][2] + bb.x, 0.f) * ww.x + fmaxf(c2[i][3] + bb.y, 0.f) * ww.y;
            }
        }
        p0 += __shfl_xor_sync(~0u, p0, 1);  p0 += __shfl_xor_sync(~0u, p0, 2);
        p1 += __shfl_xor_sync(~0u, p1, 1);  p1 += __shfl_xor_sync(~0u, p1, 2);
        if (qc == 0) {
            out[(size_t)(rowbase + qr) * 64 + r + 1]     = p0 + b3v;
            out[(size_t)(rowbase + qr + 8) * 64 + r + 1] = p1 + b3v;
        }
    }
}

extern "C" void kernel_launch(void* const* d_in, const int* in_sizes, int n_in,
                              void* d_out, int out_size) {
    const float* inputs = (const float*)d_in[0];
    const float* W1  = (const float*)d_in[1];
    const float* b1  = (const float*)d_in[2];
    const float* W2  = (const float*)d_in[3];
    const float* b2  = (const float*)d_in[4];
    const float* W3  = (const float*)d_in[5];
    const float* b3  = (const float*)d_in[6];
    const float* w01 = (const float*)d_in[7];
    const float* b01 = (const float*)d_in[8];
    const float* w02 = (const float*)d_in[9];
    const float* b02 = (const float*)d_in[10];
    const float* w03 = (const float*)d_in[11];
    const float* b03 = (const float*)d_in[12];
    float* out = (float*)d_out;

    prep_kernel<<<NMLP, THREADS>>>(W1, W2, w01, b01, w02, b02, w03, b03);

    cudaFuncSetAttribute(mlplist_kernel,
                         cudaFuncAttributeMaxDynamicSharedMemorySize, SMEM_BYTES);
    mlplist_kernel<<<NTILES, THREADS, SMEM_BYTES>>>(
        inputs, b1, b2, W3, b3, out);
}